// round 3
// baseline (speedup 1.0000x reference)
#include <cuda_runtime.h>
#include <math.h>

#define NSTEPS 8760
#define NGRID  2048
#define NMUL   2
#define LENF   72
#define DTC    (1.0f/24.0f)
#define NVEC   (NSTEPS/4)     /* 2190 */

// Scratch (device globals: no allocation allowed in kernel_launch)
__device__ float g_pT[NGRID * NSTEPS];          // transposed forcing [g][t]
__device__ float g_tT[NGRID * NSTEPS];
__device__ float g_eT[NGRID * NSTEPS];
__device__ float g_q2[NGRID * NMUL * NSTEPS];   // per-thread row [tid][t]
__device__ float g_w[LENF * NGRID];             // gamma weights [k][g]

__device__ __forceinline__ float flg2(float x) {
    float y; asm("lg2.approx.f32 %0, %1;" : "=f"(y) : "f"(x)); return y;
}
__device__ __forceinline__ float fex2(float x) {
    float y; asm("ex2.approx.f32 %0, %1;" : "=f"(y) : "f"(x)); return y;
}

// ---------------------------------------------------------------------------
// Stage 0: transpose forcing [t][g] -> [g][t]  (32x32 tiles, z selects array)
// ---------------------------------------------------------------------------
__global__ void __launch_bounds__(256) transpose_kernel(
    const float* __restrict__ prcp,
    const float* __restrict__ tmean,
    const float* __restrict__ pet)
{
    __shared__ float tile[32][33];
    const float* in;
    float* out;
    switch (blockIdx.z) {
        case 0:  in = prcp;  out = g_pT; break;
        case 1:  in = tmean; out = g_tT; break;
        default: in = pet;   out = g_eT; break;
    }
    const int tx = threadIdx.x, ty = threadIdx.y;        // block (32, 8)
    const int g0 = blockIdx.x * 32;
    const int t0 = blockIdx.y * 32;

#pragma unroll
    for (int r = 0; r < 32; r += 8) {
        int t = t0 + ty + r;
        tile[ty + r][tx] = (t < NSTEPS) ? in[t * NGRID + g0 + tx] : 0.0f;
    }
    __syncthreads();
#pragma unroll
    for (int r = 0; r < 32; r += 8) {
        int t = t0 + tx;
        if (t < NSTEPS)
            out[(size_t)(g0 + ty + r) * NSTEPS + t] = tile[tx][ty + r];
    }
}

// ---------------------------------------------------------------------------
// Stage 1: HBV scan. One thread per (grid, mul); 4096 threads on 128 SMs.
// Forcing read as float4 from transposed layout; Q written as float4.
// ---------------------------------------------------------------------------
__global__ void __launch_bounds__(32) hbv_scan_kernel(const float* __restrict__ phy)
{
    const int tid = blockIdx.x * 32 + threadIdx.x;   // 0..4095
    const int g = tid >> 1;
    const int m = tid & 1;

    const float lb[19] = {1.0f, 50.0f, 0.05f, 0.01f, 0.001f, 0.2f, 0.0f, 0.0f,
                          -2.5f, 0.5f, 0.0f, 0.0f, 0.3f, 0.0f, 0.0f, 0.0f,
                          5.0f/DTC, 0.0f, 0.5f};
    const float ub[19] = {6.0f, 1000.0f, 0.9f, 0.5f, 0.2f, 1.0f, 10.0f, 100.0f,
                          2.5f, 10.0f, 0.1f, 0.2f, 5.0f, 1.0f, 20.0f, 2500.0f,
                          120.0f/DTC, 1.0f, 5.0f};
    float pp[19];
#pragma unroll
    for (int i = 0; i < 19; i++) {
        float r = phy[g * (19 * NMUL) + i * NMUL + m];
        pp[i] = lb[i] + r * (ub[i] - lb[i]);
    }
    const float BETA   = pp[0];
    const float FC     = pp[1];
    const float UZL    = pp[7];
    const float TTp    = pp[8];
    const float CWH    = pp[11];
    const float BETAET = pp[12];
    const float Cc     = pp[13];
    const float FMIN   = pp[17];
    const float ALPHA  = pp[18];

    const float invFC       = 1.0f / FC;
    const float k0dt        = pp[2] * DTC;
    const float k1dt        = pp[3] * DTC;
    const float k2dt        = pp[4] * DTC;
    const float percdt      = pp[6] * DTC;
    const float cfmaxdt     = pp[9] * DTC;
    const float cfrcfmaxdt  = pp[10] * cfmaxdt;
    const float f0dt        = pp[16] * DTC;
    const float fmin_f0dt   = FMIN * f0dt;
    const float omfmin_f0dt = (1.0f - FMIN) * f0dt;
    const float evap_c      = BETAET * flg2(1.0f / (pp[5] * FC));

    float SP = 0.001f, MW = 0.001f, SM = 0.001f, SUZ = 0.001f, SLZ = 0.001f;
    float CcSLZ = Cc * 0.001f;          // Cc*SLZ maintained off the SM-chain

    const float4* Pv = reinterpret_cast<const float4*>(g_pT + (size_t)g * NSTEPS);
    const float4* Tv = reinterpret_cast<const float4*>(g_tT + (size_t)g * NSTEPS);
    const float4* Ev = reinterpret_cast<const float4*>(g_eT + (size_t)g * NSTEPS);
    float4*       Qv = reinterpret_cast<float4*>(g_q2) + (size_t)tid * NVEC;

    // one HBV step; returns Q for the step
    auto step = [&](float P, float T, float PV) -> float {
        // snow (short, parallel chain)
        float SNOW = (T < TTp) ? P : 0.0f;
        float RAIN = P - SNOW;
        float SP1  = SP + SNOW;
        float melt = fminf(fmaxf(cfmaxdt * (T - TTp), 0.0f), SP1);
        float MW1  = MW + melt;
        float SP2  = SP1 - melt;
        float refr = fminf(fmaxf(cfrcfmaxdt * (TTp - T), 0.0f), MW1);
        SP = SP2 + refr;
        float MW2    = MW1 - refr;
        float tosoil = fmaxf(fmaf(-CWH, SP, MW2), 0.0f);
        MW = MW2 - tosoil;
        float win = RAIN + tosoil;

        // soil moisture (critical carry cycle)
        float ratio = SM * invFC;
        float omr   = fmaxf(1.0f - ratio, 1e-6f);
        float fcap  = fmaf(omfmin_f0dt, fex2(ALPHA * flg2(omr)), fmin_f0dt);
        float infil = fminf(win, fcap);
        float soilw = fminf(fex2(BETA * flg2(ratio)), 1.0f);
        float SM1   = fmaf(infil, 1.0f - soilw, SM);
        float SM2   = fminf(SM1, FC);
        float e     = fex2(fmaf(flg2(SM2), BETAET, evap_c));
        float x     = fminf(PV * e, PV);            // == PV * min(e, 1)
        float SM3   = fmaxf(SM2 - x, 1e-5f);        // == max(SM2 - AET, 1e-5)
        float w1    = fmaf(-invFC, SM3, 1.0f);      // 1 - SM3/FC, in [0,1]
        float cap   = CcSLZ * w1;
        SM = SM3 + cap;

        // zones (off the SM-chain)
        float rech = infil * soilw;
        float excs = SM1 - SM2;
        float surf = win - infil;
        float SUZ1 = SUZ + (rech + excs) + surf;
        float perc = fminf(SUZ1, percdt);
        float SUZ2 = SUZ1 - perc;
        float Q0   = k0dt * fmaxf(SUZ2 - UZL, 0.0f);
        float SUZ3 = SUZ2 - Q0;
        float Q1   = k1dt * SUZ3;
        SUZ = SUZ3 - Q1;
        float SLZ1 = (SLZ - cap) + perc;
        float Q2   = k2dt * SLZ1;
        SLZ = SLZ1 - Q2;
        CcSLZ = Cc * SLZ;
        return Q0 + Q1 + Q2;
    };

    float4 P0 = Pv[0], T0 = Tv[0], E0 = Ev[0];
    float4 P1 = Pv[1], T1 = Tv[1], E1 = Ev[1];

    for (int b = 0; b < NVEC; b++) {
        int ip = min(b + 2, NVEC - 1);               // branch-free prefetch
        float4 P2 = Pv[ip], T2 = Tv[ip], E2 = Ev[ip];

        float4 q4;
        q4.x = step(P0.x, T0.x, E0.x);
        q4.y = step(P0.y, T0.y, E0.y);
        q4.z = step(P0.z, T0.z, E0.z);
        q4.w = step(P0.w, T0.w, E0.w);
        Qv[b] = q4;

        P0 = P1; T0 = T1; E0 = E1;
        P1 = P2; T1 = T2; E1 = E2;
    }
}

// ---------------------------------------------------------------------------
// Stage 2: gamma routing weights, one thread per grid.
// ---------------------------------------------------------------------------
__global__ void __launch_bounds__(128) weights_kernel(const float* __restrict__ distr)
{
    int g = blockIdx.x * blockDim.x + threadIdx.x;
    if (g >= NGRID) return;

    float aa  = fmaxf(distr[g * 3 + 0] * 5.0f,  0.0f) + 0.1f;
    float th  = fmaxf(distr[g * 3 + 1] * 12.0f, 0.0f) + 0.5f;
    float tau = distr[g * 3 + 2] * 48.0f;

    float lga   = lgammaf(aa);
    float lth   = logf(th);
    float invth = 1.0f / th;
    float am1   = aa - 1.0f;

    float ws[LENF];
    float s = 0.0f;
#pragma unroll
    for (int k = 0; k < LENF; k++) {
        float t  = (float)k + 0.5f;
        float ts = fmaxf(t - tau, 0.001f);
        float lw = -lga - aa * lth + am1 * logf(ts) - ts * invth;
        float w  = expf(lw);
        ws[k] = w;
        s += w;
    }
    float inv = 1.0f / s;
#pragma unroll
    for (int k = 0; k < LENF; k++)
        g_w[k * NGRID + g] = ws[k] * inv;
}

// ---------------------------------------------------------------------------
// Stage 3: 72-tap FIR. Tile 32 grids x 64 t; q rows are [tid][t] so the mul
// pair is averaged at load (contiguous row pair). Register rolling window.
// ---------------------------------------------------------------------------
#define CONV_GT   32
#define CONV_TT   64
#define CONV_RPT  8
#define CONV_QS   (CONV_TT + LENF - 1)   /* 135 */

__global__ void __launch_bounds__(256) conv_kernel(float* __restrict__ out)
{
    __shared__ float q_sh[CONV_QS][CONV_GT + 1];   // padded: conflict-free both ways
    __shared__ float w_sh[LENF][CONV_GT];

    const int tid   = threadIdx.x;
    const int lane  = tid & 31;
    const int wpid  = tid >> 5;                    // 8 warps
    const int gbase = blockIdx.x * CONV_GT;
    const int t0    = blockIdx.y * CONV_TT;

    // each warp loads 4 g-rows; per row, lanes stride over t (coalesced)
#pragma unroll
    for (int k = 0; k < 4; k++) {
        int gl = wpid * 4 + k;
        const float* r0 = g_q2 + (size_t)(2 * (gbase + gl)) * NSTEPS;
        const float* r1 = r0 + NSTEPS;
        for (int tt = lane; tt < CONV_QS; tt += 32) {
            int tq = t0 - (LENF - 1) + tt;
            float v = 0.0f;
            if (tq >= 0 && tq < NSTEPS) v = 0.5f * (r0[tq] + r1[tq]);
            q_sh[tt][gl] = v;
        }
    }
    for (int idx = tid; idx < LENF * CONV_GT; idx += 256) {
        int k = idx >> 5, c = idx & 31;
        w_sh[k][c] = g_w[k * NGRID + gbase + c];
    }
    __syncthreads();

    const int tx   = lane;
    const int trow = wpid * CONV_RPT;

    float acc[CONV_RPT];
#pragma unroll
    for (int r = 0; r < CONV_RPT; r++) acc[r] = 0.0f;

    float buf[CONV_RPT];                  // mod-8 register ring
#pragma unroll
    for (int i = 0; i < CONV_RPT; i++)
        buf[(LENF - 1 + i) & 7] = q_sh[trow + LENF - 1 + i][tx];

#pragma unroll
    for (int k = 0; k < LENF; k++) {
        float wv = w_sh[k][tx];
#pragma unroll
        for (int r = 0; r < CONV_RPT; r++)
            acc[r] += wv * buf[(LENF - 1 - k + r) & 7];
        if (k < LENF - 1)
            buf[(LENF - 2 - k) & 7] = q_sh[trow + LENF - 2 - k][tx];
    }

#pragma unroll
    for (int r = 0; r < CONV_RPT; r++) {
        int t = t0 + trow + r;
        if (t < NSTEPS)
            out[t * NGRID + gbase + tx] = acc[r];
    }
}

// ---------------------------------------------------------------------------
extern "C" void kernel_launch(void* const* d_in, const int* in_sizes, int n_in,
                              void* d_out, int out_size)
{
    const float* prcp  = (const float*)d_in[0];
    const float* tmean = (const float*)d_in[1];
    const float* pet   = (const float*)d_in[2];
    const float* phy   = (const float*)d_in[3];
    const float* distr = (const float*)d_in[4];
    float* out = (float*)d_out;

    dim3 tb(32, 8);
    dim3 tg(NGRID / 32, (NSTEPS + 31) / 32, 3);
    transpose_kernel<<<tg, tb>>>(prcp, tmean, pet);

    weights_kernel<<<(NGRID + 127) / 128, 128>>>(distr);

    hbv_scan_kernel<<<(NGRID * NMUL) / 32, 32>>>(phy);

    dim3 gc(NGRID / CONV_GT, (NSTEPS + CONV_TT - 1) / CONV_TT);
    conv_kernel<<<gc, 256>>>(out);
}